// round 2
// baseline (speedup 1.0000x reference)
#include <cuda_runtime.h>
#include <cuda_bf16.h>
#include <cstdint>

#define B_ 8
#define S_ 4096
#define D_ 64
#define BQ 128          // q rows per block
#define BK 128          // k cols per tile
#define NTHREADS 256

// smem strides (floats), padded
#define QST_LD 132      // Qst [64][132]  layout [d][q]
#define KST_LD 132      // Kst [64][132]  layout [d][k]
#define PS_LD  132      // Ps  [128][132] layout [k][q]
#define VS_LD  68       // Vs  [128][68]  layout [k][d]

#define SMEM_FLOATS (64*QST_LD + 64*KST_LD + 128*PS_LD + 128*VS_LD + 128)
#define SMEM_BYTES  (SMEM_FLOATS * 4)

__device__ float g_rowsum[(size_t)B_ * S_];

__global__ __launch_bounds__(NTHREADS, 1)
void attn_main_kernel(const float* __restrict__ Q,
                      const float* __restrict__ K,
                      const float* __restrict__ V,
                      const int* __restrict__ mask,
                      float* __restrict__ ctx_out,
                      float* __restrict__ attn_out)
{
    extern __shared__ float sm[];
    float* Qst = sm;                       // [64][QST_LD]
    float* Kst = Qst + 64 * QST_LD;        // [64][KST_LD]
    float* Ps  = Kst + 64 * KST_LD;        // [128][PS_LD]
    float* Vs  = Ps  + 128 * PS_LD;        // [128][VS_LD]
    float* rss = Vs  + 128 * VS_LD;        // [128]

    const int b   = blockIdx.y;
    const int q0  = blockIdx.x * BQ;
    const int tid = threadIdx.x;
    const int tx  = tid & 15;              // QK: k-group (8 k each). PV: d-group (4 d each)
    const int ty  = tid >> 4;              // q-group (8 q each)

    const float* Qg = Q + ((size_t)b * S_ + q0) * D_;

    // ---- load Q tile transposed into Qst[d][q] ----
    #pragma unroll
    for (int it = 0; it < (BQ * D_ / 4) / NTHREADS; ++it) {
        int idx = (it * NTHREADS + tid) * 4;
        int q = idx >> 6;
        int d = idx & 63;
        float4 v = *reinterpret_cast<const float4*>(Qg + q * D_ + d);
        Qst[(d + 0) * QST_LD + q] = v.x;
        Qst[(d + 1) * QST_LD + q] = v.y;
        Qst[(d + 2) * QST_LD + q] = v.z;
        Qst[(d + 3) * QST_LD + q] = v.w;
    }
    if (tid < BQ) rss[tid] = 0.0f;

    float ctx[8][4];
    #pragma unroll
    for (int i = 0; i < 8; ++i)
        #pragma unroll
        for (int j = 0; j < 4; ++j) ctx[i][j] = 0.0f;
    float rs[8] = {0,0,0,0,0,0,0,0};

    __syncthreads();

    for (int k0 = 0; k0 < S_; k0 += BK) {
        // ---- load K tile (transposed) and V tile ----
        const float* Kg = K + ((size_t)b * S_ + k0) * D_;
        const float* Vg = V + ((size_t)b * S_ + k0) * D_;
        #pragma unroll
        for (int it = 0; it < (BK * D_ / 4) / NTHREADS; ++it) {
            int idx = (it * NTHREADS + tid) * 4;
            int k = idx >> 6;
            int d = idx & 63;
            float4 kv = *reinterpret_cast<const float4*>(Kg + k * D_ + d);
            Kst[(d + 0) * KST_LD + k] = kv.x;
            Kst[(d + 1) * KST_LD + k] = kv.y;
            Kst[(d + 2) * KST_LD + k] = kv.z;
            Kst[(d + 3) * KST_LD + k] = kv.w;
            float4 vv = *reinterpret_cast<const float4*>(Vg + k * D_ + d);
            *reinterpret_cast<float4*>(Vs + k * VS_LD + d) = vv;
        }
        __syncthreads();

        // ---- QK^T: 8x8 micro-tile per thread ----
        float p[8][8];
        #pragma unroll
        for (int i = 0; i < 8; ++i)
            #pragma unroll
            for (int j = 0; j < 8; ++j) p[i][j] = 0.0f;

        #pragma unroll 8
        for (int d = 0; d < 64; ++d) {
            float4 a0 = *reinterpret_cast<const float4*>(Qst + d * QST_LD + 8 * ty);
            float4 a1 = *reinterpret_cast<const float4*>(Qst + d * QST_LD + 8 * ty + 4);
            float4 b0 = *reinterpret_cast<const float4*>(Kst + d * KST_LD + 8 * tx);
            float4 b1 = *reinterpret_cast<const float4*>(Kst + d * KST_LD + 8 * tx + 4);
            float a[8] = {a0.x, a0.y, a0.z, a0.w, a1.x, a1.y, a1.z, a1.w};
            float bb[8] = {b0.x, b0.y, b0.z, b0.w, b1.x, b1.y, b1.z, b1.w};
            #pragma unroll
            for (int i = 0; i < 8; ++i)
                #pragma unroll
                for (int j = 0; j < 8; ++j)
                    p[i][j] += a[i] * bb[j];
        }

        // ---- mask (int32 per element!) + exp ----
        // masked (nonzero) -> prob exactly 0, matching exp(-10000 - max) == 0
        #pragma unroll
        for (int i = 0; i < 8; ++i) {
            int q = q0 + 8 * ty + i;
            size_t off = ((size_t)b * S_ + q) * S_ + k0 + 8 * tx;
            int4 m0 = *reinterpret_cast<const int4*>(mask + off);
            int4 m1 = *reinterpret_cast<const int4*>(mask + off + 4);
            int mv[8] = {m0.x, m0.y, m0.z, m0.w, m1.x, m1.y, m1.z, m1.w};
            float r[8];
            #pragma unroll
            for (int j = 0; j < 8; ++j)
                r[j] = (mv[j] != 0) ? 0.0f : __expf(p[i][j] * 0.125f);
            rs[i] += ((r[0] + r[1]) + (r[2] + r[3])) + ((r[4] + r[5]) + (r[6] + r[7]));
            // unnormalized probs -> attn output (kernel 2 normalizes)
            *reinterpret_cast<float4*>(attn_out + off)     = make_float4(r[0], r[1], r[2], r[3]);
            *reinterpret_cast<float4*>(attn_out + off + 4) = make_float4(r[4], r[5], r[6], r[7]);
            #pragma unroll
            for (int j = 0; j < 8; ++j) p[i][j] = r[j];
        }

        // ---- store P transposed to smem: Ps[k][q] ----
        #pragma unroll
        for (int j = 0; j < 8; ++j) {
            *reinterpret_cast<float4*>(Ps + (8 * tx + j) * PS_LD + 8 * ty) =
                make_float4(p[0][j], p[1][j], p[2][j], p[3][j]);
            *reinterpret_cast<float4*>(Ps + (8 * tx + j) * PS_LD + 8 * ty + 4) =
                make_float4(p[4][j], p[5][j], p[6][j], p[7][j]);
        }
        __syncthreads();

        // ---- P·V: 8x4 micro-tile per thread (q = 8*ty+i, d = 4*tx+j) ----
        #pragma unroll 8
        for (int k = 0; k < BK; ++k) {
            float4 vv = *reinterpret_cast<const float4*>(Vs + k * VS_LD + 4 * tx);
            float4 pa = *reinterpret_cast<const float4*>(Ps + k * PS_LD + 8 * ty);
            float4 pb = *reinterpret_cast<const float4*>(Ps + k * PS_LD + 8 * ty + 4);
            float pr[8] = {pa.x, pa.y, pa.z, pa.w, pb.x, pb.y, pb.z, pb.w};
            float vj[4] = {vv.x, vv.y, vv.z, vv.w};
            #pragma unroll
            for (int i = 0; i < 8; ++i)
                #pragma unroll
                for (int j = 0; j < 4; ++j)
                    ctx[i][j] += pr[i] * vj[j];
        }
        __syncthreads();
    }

    // ---- row-sum reduction across tx ----
    #pragma unroll
    for (int i = 0; i < 8; ++i)
        atomicAdd(&rss[8 * ty + i], rs[i]);
    __syncthreads();

    if (tid < BQ)
        g_rowsum[(size_t)b * S_ + q0 + tid] = rss[tid];

    // ---- normalized context out ----
    #pragma unroll
    for (int i = 0; i < 8; ++i) {
        float s = 1.0f / rss[8 * ty + i];
        float4 o = make_float4(ctx[i][0] * s, ctx[i][1] * s, ctx[i][2] * s, ctx[i][3] * s);
        *reinterpret_cast<float4*>(ctx_out + ((size_t)b * S_ + q0 + 8 * ty + i) * D_ + 4 * tx) = o;
    }
}

__global__ void attn_norm_kernel(float* __restrict__ attn)
{
    const size_t n4 = (size_t)B_ * S_ * S_ / 4;
    for (size_t i = (size_t)blockIdx.x * blockDim.x + threadIdx.x;
         i < n4;
         i += (size_t)gridDim.x * blockDim.x) {
        float4 v = reinterpret_cast<const float4*>(attn)[i];
        size_t row = i >> 10;                 // (i*4) / S_
        float s = __fdividef(1.0f, g_rowsum[row]);
        v.x *= s; v.y *= s; v.z *= s; v.w *= s;
        reinterpret_cast<float4*>(attn)[i] = v;
    }
}

extern "C" void kernel_launch(void* const* d_in, const int* in_sizes, int n_in,
                              void* d_out, int out_size)
{
    const float* Q = (const float*)d_in[0];
    const float* K = (const float*)d_in[1];
    const float* V = (const float*)d_in[2];
    const int* mask = (const int*)d_in[3];

    float* ctx_out  = (float*)d_out;
    float* attn_out = ctx_out + (size_t)B_ * S_ * D_;

    static bool attr_set = false;
    if (!attr_set) {
        cudaFuncSetAttribute(attn_main_kernel,
                             cudaFuncAttributeMaxDynamicSharedMemorySize, SMEM_BYTES);
        attr_set = true;
    }

    dim3 grid(S_ / BQ, B_);
    attn_main_kernel<<<grid, NTHREADS, SMEM_BYTES>>>(Q, K, V, mask, ctx_out, attn_out);
    attn_norm_kernel<<<8192, 256>>>(attn_out);
}

// round 4
// speedup vs baseline: 1.7350x; 1.7350x over previous
#include <cuda_runtime.h>
#include <cuda_bf16.h>
#include <cstdint>

#define B_   8
#define S_   4096
#define D_HD 64
#define BQ   128
#define BK   128
#define NTH  256

// ---- smem layout (bytes). K/V bf16 tiles: 128 rows x 72 halves (144B stride) ----
#define SM_KHI 0
#define SM_KLO 18432
#define SM_VHI 36864
#define SM_VLO 55296
#define SM_RS  73728          // float[128] rowsums
#define SM_TOT 74496
// Q fp32 staging (transient, start only): overlaps KHI/KLO region, stride 68 floats
#define QS_STRIDE 68

__device__ float g_rowsum[(size_t)B_ * S_];

static __device__ __forceinline__ uint32_t smem_u32(const void* p) {
    uint32_t a;
    asm("{ .reg .u64 t; cvta.to.shared.u64 t, %1; cvt.u32.u64 %0, t; }" : "=r"(a) : "l"(p));
    return a;
}
static __device__ __forceinline__ void ldsm4(uint32_t* r, uint32_t addr) {
    asm volatile("ldmatrix.sync.aligned.m8n8.x4.shared.b16 {%0,%1,%2,%3}, [%4];"
                 : "=r"(r[0]), "=r"(r[1]), "=r"(r[2]), "=r"(r[3]) : "r"(addr));
}
static __device__ __forceinline__ void ldsm4t(uint32_t* r, uint32_t addr) {
    asm volatile("ldmatrix.sync.aligned.m8n8.x4.trans.shared.b16 {%0,%1,%2,%3}, [%4];"
                 : "=r"(r[0]), "=r"(r[1]), "=r"(r[2]), "=r"(r[3]) : "r"(addr));
}
static __device__ __forceinline__ void mma_bf16(float* c, const uint32_t* a,
                                                uint32_t b0, uint32_t b1) {
    asm volatile("mma.sync.aligned.m16n8k16.row.col.f32.bf16.bf16.f32 "
                 "{%0,%1,%2,%3}, {%4,%5,%6,%7}, {%8,%9}, {%0,%1,%2,%3};"
                 : "+f"(c[0]), "+f"(c[1]), "+f"(c[2]), "+f"(c[3])
                 : "r"(a[0]), "r"(a[1]), "r"(a[2]), "r"(a[3]), "r"(b0), "r"(b1));
}
static __device__ __forceinline__ uint32_t packbf(float a, float b) {
    __nv_bfloat162 t = __floats2bfloat162_rn(a, b);
    return *reinterpret_cast<uint32_t*>(&t);
}
static __device__ __forceinline__ float bfhi(float x) {
    return __bfloat162float(__float2bfloat16_rn(x));
}

__global__ __launch_bounds__(NTH, 1)
void attn_hmma_kernel(const float* __restrict__ Q,
                      const float* __restrict__ K,
                      const float* __restrict__ V,
                      const int*   __restrict__ mask,
                      float* __restrict__ ctx_out,
                      float* __restrict__ attn_out)
{
    extern __shared__ char smc[];
    float* smf = reinterpret_cast<float*>(smc);
    const uint32_t sb = smem_u32(smc);

    const int tid  = threadIdx.x;
    const int w    = tid >> 5;          // warp: owns q-rows [16w,16w+16)
    const int lane = tid & 31;
    const int lrow = lane & 7;
    const int lsub = lane >> 3;
    const int b    = blockIdx.y;
    const int q0   = blockIdx.x * BQ;

    // ldmatrix per-lane address components (byte offsets within a tile)
    const uint32_t kofsK = (uint32_t)((((lsub & 2) ? 8 : 0) + lrow) * 144 + ((lsub & 1) ? 16 : 0));
    const uint32_t kofsV = (uint32_t)((lrow + ((lsub & 1) ? 8 : 0)) * 144 + ((lsub & 2) ? 16 : 0));

    // ---- stage Q (scaled by 1/8) and build persistent A fragments ----
    {
        const float* Qg = Q + ((size_t)b * S_ + q0) * D_HD;
        #pragma unroll
        for (int it = 0; it < 8; ++it) {
            int idx = (it * NTH + tid) * 4;
            int q = idx >> 6, d = idx & 63;
            float4 v = *reinterpret_cast<const float4*>(Qg + idx);
            float* dst = smf + q * QS_STRIDE + d;
            dst[0] = v.x * 0.125f; dst[1] = v.y * 0.125f;
            dst[2] = v.z * 0.125f; dst[3] = v.w * 0.125f;
        }
    }
    __syncthreads();

    uint32_t qh[4][4], ql[4][4];
    {
        const int r0 = 16 * w + (lane >> 2);
        const int c0 = 2 * (lane & 3);
        #pragma unroll
        for (int kc = 0; kc < 4; ++kc) {
            #pragma unroll
            for (int f = 0; f < 4; ++f) {
                int rr = r0 + ((f & 1) ? 8 : 0);
                int cc = kc * 16 + c0 + ((f & 2) ? 8 : 0);
                float2 v = *reinterpret_cast<const float2*>(smf + rr * QS_STRIDE + cc);
                float hx = bfhi(v.x), hy = bfhi(v.y);
                qh[kc][f] = packbf(hx, hy);
                ql[kc][f] = packbf(v.x - hx, v.y - hy);
            }
        }
    }
    __syncthreads();

    float ctx[8][4];
    #pragma unroll
    for (int i = 0; i < 8; ++i)
        #pragma unroll
        for (int j = 0; j < 4; ++j) ctx[i][j] = 0.0f;
    float rs0 = 0.0f, rs1 = 0.0f;

    const size_t rowA = (size_t)b * S_ + q0 + 16 * w + (lane >> 2);
    const int    colL = 2 * (lane & 3);

    for (int t = 0; t < S_ / BK; ++t) {
        const int k0 = t << 7;
        __syncthreads();

        // ---- load + split K, V into bf16 hi/lo smem tiles ----
        const float* Kg = K + ((size_t)b * S_ + k0) * D_HD;
        const float* Vg = V + ((size_t)b * S_ + k0) * D_HD;
        #pragma unroll
        for (int it = 0; it < 8; ++it) {
            int idx = (it * NTH + tid) * 4;
            int row = idx >> 6, d = idx & 63;
            uint32_t off = (uint32_t)(row * 144 + d * 2);
            float4 kv = *reinterpret_cast<const float4*>(Kg + idx);
            float h0 = bfhi(kv.x), h1 = bfhi(kv.y), h2 = bfhi(kv.z), h3 = bfhi(kv.w);
            *reinterpret_cast<uint32_t*>(smc + SM_KHI + off)     = packbf(h0, h1);
            *reinterpret_cast<uint32_t*>(smc + SM_KHI + off + 4) = packbf(h2, h3);
            *reinterpret_cast<uint32_t*>(smc + SM_KLO + off)     = packbf(kv.x - h0, kv.y - h1);
            *reinterpret_cast<uint32_t*>(smc + SM_KLO + off + 4) = packbf(kv.z - h2, kv.w - h3);
            float4 vv = *reinterpret_cast<const float4*>(Vg + idx);
            float g0 = bfhi(vv.x), g1 = bfhi(vv.y), g2 = bfhi(vv.z), g3 = bfhi(vv.w);
            *reinterpret_cast<uint32_t*>(smc + SM_VHI + off)     = packbf(g0, g1);
            *reinterpret_cast<uint32_t*>(smc + SM_VHI + off + 4) = packbf(g2, g3);
            *reinterpret_cast<uint32_t*>(smc + SM_VLO + off)     = packbf(vv.x - g0, vv.y - g1);
            *reinterpret_cast<uint32_t*>(smc + SM_VLO + off + 4) = packbf(vv.z - g2, vv.w - g3);
        }
        __syncthreads();

        #pragma unroll
        for (int h = 0; h < 2; ++h) {
            // ---- QK^T half: scores 16q x 64k, 3 bf16 passes ----
            float sc[8][4];
            #pragma unroll
            for (int i = 0; i < 8; ++i)
                #pragma unroll
                for (int j = 0; j < 4; ++j) sc[i][j] = 0.0f;

            #pragma unroll
            for (int pass = 0; pass < 3; ++pass) {
                const uint32_t(*pa)[4] = (pass == 2) ? ql : qh;
                const uint32_t bbase = sb + ((pass == 1) ? SM_KLO : SM_KHI)
                                     + (uint32_t)(h * 64 * 144) + kofsK;
                #pragma unroll
                for (int kc = 0; kc < 4; ++kc) {
                    #pragma unroll
                    for (int ntp = 0; ntp < 4; ++ntp) {
                        uint32_t bfr[4];
                        ldsm4(bfr, bbase + (uint32_t)(ntp * 16 * 144 + kc * 32));
                        mma_bf16(sc[2 * ntp],     pa[kc], bfr[0], bfr[1]);
                        mma_bf16(sc[2 * ntp + 1], pa[kc], bfr[2], bfr[3]);
                    }
                }
            }

            // ---- mask + exp + direct attn write (sector-coalesced float2) ----
            #pragma unroll
            for (int nt = 0; nt < 8; ++nt) {
                const size_t cg = (size_t)(k0 + h * 64 + nt * 8 + colL);
                const int2 m0 = *reinterpret_cast<const int2*>(mask + rowA * S_ + cg);
                const int2 m1 = *reinterpret_cast<const int2*>(mask + (rowA + 8) * S_ + cg);
                float e0 = m0.x ? 0.0f : __expf(sc[nt][0]);
                float e1 = m0.y ? 0.0f : __expf(sc[nt][1]);
                float e2 = m1.x ? 0.0f : __expf(sc[nt][2]);
                float e3 = m1.y ? 0.0f : __expf(sc[nt][3]);
                rs0 += e0 + e1; rs1 += e2 + e3;
                *reinterpret_cast<float2*>(attn_out + rowA * S_ + cg)       = make_float2(e0, e1);
                *reinterpret_cast<float2*>(attn_out + (rowA + 8) * S_ + cg) = make_float2(e2, e3);
                sc[nt][0] = e0; sc[nt][1] = e1; sc[nt][2] = e2; sc[nt][3] = e3;
            }

            // ---- repack P (C-layout == A-layout) into bf16 hi/lo A fragments ----
            uint32_t ph[4][4], pl[4][4];
            #pragma unroll
            for (int kcp = 0; kcp < 4; ++kcp) {
                #pragma unroll
                for (int f = 0; f < 4; ++f) {
                    const float* s = sc[2 * kcp + ((f & 2) ? 1 : 0)];
                    float x = s[(f & 1) ? 2 : 0], y = s[(f & 1) ? 3 : 1];
                    float hx = bfhi(x), hy = bfhi(y);
                    ph[kcp][f] = packbf(hx, hy);
                    pl[kcp][f] = packbf(x - hx, y - hy);
                }
            }

            // ---- P·V half: ctx += PhVh + PlVh + PhVl ----
            const uint32_t vhb = sb + SM_VHI + (uint32_t)(h * 64 * 144) + kofsV;
            const uint32_t vlb = sb + SM_VLO + (uint32_t)(h * 64 * 144) + kofsV;
            #pragma unroll
            for (int kcp = 0; kcp < 4; ++kcp) {
                uint32_t vf[4];
                #pragma unroll
                for (int ntp = 0; ntp < 4; ++ntp) {
                    ldsm4t(vf, vhb + (uint32_t)(kcp * 16 * 144 + ntp * 32));
                    mma_bf16(ctx[2 * ntp],     ph[kcp], vf[0], vf[1]);
                    mma_bf16(ctx[2 * ntp + 1], ph[kcp], vf[2], vf[3]);
                    mma_bf16(ctx[2 * ntp],     pl[kcp], vf[0], vf[1]);
                    mma_bf16(ctx[2 * ntp + 1], pl[kcp], vf[2], vf[3]);
                }
                #pragma unroll
                for (int ntp = 0; ntp < 4; ++ntp) {
                    ldsm4t(vf, vlb + (uint32_t)(kcp * 16 * 144 + ntp * 32));
                    mma_bf16(ctx[2 * ntp],     ph[kcp], vf[0], vf[1]);
                    mma_bf16(ctx[2 * ntp + 1], ph[kcp], vf[2], vf[3]);
                }
            }
        }
    }

    // ---- rowsums: reduce over 4-lane quad, publish, normalize ctx ----
    rs0 += __shfl_xor_sync(0xffffffffu, rs0, 1);
    rs0 += __shfl_xor_sync(0xffffffffu, rs0, 2);
    rs1 += __shfl_xor_sync(0xffffffffu, rs1, 1);
    rs1 += __shfl_xor_sync(0xffffffffu, rs1, 2);
    __syncthreads();
    float* rsum = reinterpret_cast<float*>(smc + SM_RS);
    if ((lane & 3) == 0) {
        rsum[16 * w + (lane >> 2)]     = rs0;
        rsum[16 * w + (lane >> 2) + 8] = rs1;
    }
    __syncthreads();
    if (tid < BQ) g_rowsum[(size_t)b * S_ + q0 + tid] = rsum[tid];

    const float inv0 = 1.0f / rsum[16 * w + (lane >> 2)];
    const float inv1 = 1.0f / rsum[16 * w + (lane >> 2) + 8];
    #pragma unroll
    for (int nt = 0; nt < 8; ++nt) {
        int d = nt * 8 + colL;
        *reinterpret_cast<float2*>(ctx_out + rowA * D_HD + d) =
            make_float2(ctx[nt][0] * inv0, ctx[nt][1] * inv0);
        *reinterpret_cast<float2*>(ctx_out + (rowA + 8) * D_HD + d) =
            make_float2(ctx[nt][2] * inv1, ctx[nt][3] * inv1);
    }
}

__global__ void attn_norm_kernel(float* __restrict__ attn)
{
    const size_t n4 = (size_t)B_ * S_ * S_ / 4;
    for (size_t i = (size_t)blockIdx.x * blockDim.x + threadIdx.x;
         i < n4; i += (size_t)gridDim.x * blockDim.x) {
        float4 v = reinterpret_cast<const float4*>(attn)[i];
        size_t row = i >> 10;
        float s = __fdividef(1.0f, g_rowsum[row]);
        v.x *= s; v.y *= s; v.z *= s; v.w *= s;
        reinterpret_cast<float4*>(attn)[i] = v;
    }
}

extern "C" void kernel_launch(void* const* d_in, const int* in_sizes, int n_in,
                              void* d_out, int out_size)
{
    const float* Q = (const float*)d_in[0];
    const float* K = (const float*)d_in[1];
    const float* V = (const float*)d_in[2];
    const int* mask = (const int*)d_in[3];

    float* ctx_out  = (float*)d_out;
    float* attn_out = ctx_out + (size_t)B_ * S_ * D_HD;

    static bool attr_set = false;
    if (!attr_set) {
        cudaFuncSetAttribute(attn_hmma_kernel,
                             cudaFuncAttributeMaxDynamicSharedMemorySize, SM_TOT);
        attr_set = true;
    }

    dim3 grid(S_ / BQ, B_);
    attn_hmma_kernel<<<grid, NTH, SM_TOT>>>(Q, K, V, mask, ctx_out, attn_out);
    attn_norm_kernel<<<8192, 256>>>(attn_out);
}

// round 5
// speedup vs baseline: 1.8840x; 1.0859x over previous
#include <cuda_runtime.h>
#include <cuda_bf16.h>
#include <cstdint>

#define B_   8
#define S_   4096
#define D_HD 64
#define BQ   128
#define BK   128
#define NTH  256

// ---- pipelined smem: 2 stages x 4 tiles(18432B each: khi,klo,vhi,vlo) ----
#define STAGE_BYTES 73728
#define OFF_KHI 0
#define OFF_KLO 18432
#define OFF_VHI 36864
#define OFF_VLO 55296
#define SM_RS   147456           // float[128]
#define SM_TOT  147968
#define QS_STRIDE 68             // Q fp32 staging (transient, inside stage1)

// pre-split K/V in tile-ready layout: [b*S + row][72 halves] (144B row stride)
#define GROW 72
__device__ __align__(16) __nv_bfloat16 g_khi[(size_t)B_ * S_ * GROW];
__device__ __align__(16) __nv_bfloat16 g_klo[(size_t)B_ * S_ * GROW];
__device__ __align__(16) __nv_bfloat16 g_vhi[(size_t)B_ * S_ * GROW];
__device__ __align__(16) __nv_bfloat16 g_vlo[(size_t)B_ * S_ * GROW];
__device__ float g_rowsum[(size_t)B_ * S_];

static __device__ __forceinline__ uint32_t smem_u32(const void* p) {
    uint32_t a;
    asm("{ .reg .u64 t; cvta.to.shared.u64 t, %1; cvt.u32.u64 %0, t; }" : "=r"(a) : "l"(p));
    return a;
}
static __device__ __forceinline__ void ldsm4(uint32_t* r, uint32_t addr) {
    asm volatile("ldmatrix.sync.aligned.m8n8.x4.shared.b16 {%0,%1,%2,%3}, [%4];"
                 : "=r"(r[0]), "=r"(r[1]), "=r"(r[2]), "=r"(r[3]) : "r"(addr));
}
static __device__ __forceinline__ void ldsm4t(uint32_t* r, uint32_t addr) {
    asm volatile("ldmatrix.sync.aligned.m8n8.x4.trans.shared.b16 {%0,%1,%2,%3}, [%4];"
                 : "=r"(r[0]), "=r"(r[1]), "=r"(r[2]), "=r"(r[3]) : "r"(addr));
}
static __device__ __forceinline__ void mma_bf16(float* c, const uint32_t* a,
                                                uint32_t b0, uint32_t b1) {
    asm volatile("mma.sync.aligned.m16n8k16.row.col.f32.bf16.bf16.f32 "
                 "{%0,%1,%2,%3}, {%4,%5,%6,%7}, {%8,%9}, {%0,%1,%2,%3};"
                 : "+f"(c[0]), "+f"(c[1]), "+f"(c[2]), "+f"(c[3])
                 : "r"(a[0]), "r"(a[1]), "r"(a[2]), "r"(a[3]), "r"(b0), "r"(b1));
}
static __device__ __forceinline__ uint32_t packbf(float a, float b) {
    __nv_bfloat162 t = __floats2bfloat162_rn(a, b);
    return *reinterpret_cast<uint32_t*>(&t);
}
static __device__ __forceinline__ float bfhi(float x) {
    return __bfloat162float(__float2bfloat16_rn(x));
}

// ---- one-time split of K/V into tile-ready bf16 hi/lo gmem ----
__global__ __launch_bounds__(NTH)
void prep_split_kernel(const float* __restrict__ K, const float* __restrict__ V)
{
    size_t idx = (size_t)blockIdx.x * NTH + threadIdx.x;   // float4 index
    size_t row = idx >> 4;
    int d4 = (int)(idx & 15);
    size_t dst = row * GROW + (size_t)d4 * 4;

    float4 kv = reinterpret_cast<const float4*>(K)[idx];
    float h0 = bfhi(kv.x), h1 = bfhi(kv.y), h2 = bfhi(kv.z), h3 = bfhi(kv.w);
    *reinterpret_cast<uint2*>(&g_khi[dst]) = make_uint2(packbf(h0, h1), packbf(h2, h3));
    *reinterpret_cast<uint2*>(&g_klo[dst]) =
        make_uint2(packbf(kv.x - h0, kv.y - h1), packbf(kv.z - h2, kv.w - h3));

    float4 vv = reinterpret_cast<const float4*>(V)[idx];
    float g0 = bfhi(vv.x), g1 = bfhi(vv.y), g2 = bfhi(vv.z), g3 = bfhi(vv.w);
    *reinterpret_cast<uint2*>(&g_vhi[dst]) = make_uint2(packbf(g0, g1), packbf(g2, g3));
    *reinterpret_cast<uint2*>(&g_vlo[dst]) =
        make_uint2(packbf(vv.x - g0, vv.y - g1), packbf(vv.z - g2, vv.w - g3));
}

__global__ __launch_bounds__(NTH, 1)
void attn_hmma_kernel(const float* __restrict__ Q,
                      const int*   __restrict__ mask,
                      float* __restrict__ ctx_out,
                      float* __restrict__ attn_out)
{
    extern __shared__ char smc[];
    const uint32_t sb = smem_u32(smc);

    const int tid  = threadIdx.x;
    const int w    = tid >> 5;
    const int lane = tid & 31;
    const int lrow = lane & 7;
    const int lsub = lane >> 3;
    const int b    = blockIdx.y;
    const int q0   = blockIdx.x * BQ;

    const uint32_t kofsK = (uint32_t)((((lsub & 2) ? 8 : 0) + lrow) * 144 + ((lsub & 1) ? 16 : 0));
    const uint32_t kofsV = (uint32_t)((lrow + ((lsub & 1) ? 8 : 0)) * 144 + ((lsub & 2) ? 16 : 0));

    // async copy of one k-tile (4 sub-tiles of 18432B) into stage buffer
    auto issue_copy = [&](int t, int buf) {
        size_t gbase = ((size_t)b * S_ + (size_t)t * BK) * GROW;   // halves
        const __nv_bfloat16* gp[4] = { g_khi + gbase, g_klo + gbase,
                                       g_vhi + gbase, g_vlo + gbase };
        uint32_t s0 = sb + (uint32_t)buf * STAGE_BYTES;
        #pragma unroll
        for (int a = 0; a < 4; ++a) {
            uint64_t ga = (uint64_t)__cvta_generic_to_global(gp[a]);
            uint32_t sa = s0 + (uint32_t)a * 18432u;
            #pragma unroll
            for (int i = 0; i < 4; ++i) {
                uint32_t o = (uint32_t)(tid + i * NTH) * 16u;
                asm volatile("cp.async.cg.shared.global [%0], [%1], 16;"
                             :: "r"(sa + o), "l"(ga + o));
            }
            if (tid < 128) {
                uint32_t o = (uint32_t)(1024 + tid) * 16u;
                asm volatile("cp.async.cg.shared.global [%0], [%1], 16;"
                             :: "r"(sa + o), "l"(ga + o));
            }
        }
        asm volatile("cp.async.commit_group;" ::: "memory");
    };

    // prologue: start tile 0 into stage 0, stage Q fp32 into stage-1 region
    issue_copy(0, 0);
    {
        float* smf = reinterpret_cast<float*>(smc + STAGE_BYTES);
        const float* Qg = Q + ((size_t)b * S_ + q0) * D_HD;
        #pragma unroll
        for (int it = 0; it < 8; ++it) {
            int idx = (it * NTH + tid) * 4;
            int q = idx >> 6, d = idx & 63;
            float4 v = *reinterpret_cast<const float4*>(Qg + idx);
            float* dst = smf + q * QS_STRIDE + d;
            dst[0] = v.x * 0.125f; dst[1] = v.y * 0.125f;
            dst[2] = v.z * 0.125f; dst[3] = v.w * 0.125f;
        }
    }
    __syncthreads();

    uint32_t qh[4][4], ql[4][4];
    {
        const float* smf = reinterpret_cast<const float*>(smc + STAGE_BYTES);
        const int r0 = 16 * w + (lane >> 2);
        const int c0 = 2 * (lane & 3);
        #pragma unroll
        for (int kc = 0; kc < 4; ++kc) {
            #pragma unroll
            for (int f = 0; f < 4; ++f) {
                int rr = r0 + ((f & 1) ? 8 : 0);
                int cc = kc * 16 + c0 + ((f & 2) ? 8 : 0);
                float2 v = *reinterpret_cast<const float2*>(smf + rr * QS_STRIDE + cc);
                float hx = bfhi(v.x), hy = bfhi(v.y);
                qh[kc][f] = packbf(hx, hy);
                ql[kc][f] = packbf(v.x - hx, v.y - hy);
            }
        }
    }
    __syncthreads();   // Q-staging region free; stage-1 may now be overwritten

    float ctx[8][4];
    #pragma unroll
    for (int i = 0; i < 8; ++i)
        #pragma unroll
        for (int j = 0; j < 4; ++j) ctx[i][j] = 0.0f;
    float rs0 = 0.0f, rs1 = 0.0f;

    const size_t rowA = (size_t)b * S_ + q0 + 16 * w + (lane >> 2);
    const int    colL = 2 * (lane & 3);

    for (int t = 0; t < S_ / BK; ++t) {
        const int buf = t & 1;
        const int k0  = t << 7;

        asm volatile("cp.async.wait_group 0;" ::: "memory");
        __syncthreads();                       // tile t resident; prev stage free
        if (t + 1 < S_ / BK) issue_copy(t + 1, (t + 1) & 1);

        const uint32_t base = sb + (uint32_t)buf * STAGE_BYTES;

        #pragma unroll
        for (int h = 0; h < 2; ++h) {
            // ---- QK^T half: 3 bf16 passes (hh + hl + lh) ----
            float sc[8][4];
            #pragma unroll
            for (int i = 0; i < 8; ++i)
                #pragma unroll
                for (int j = 0; j < 4; ++j) sc[i][j] = 0.0f;

            #pragma unroll
            for (int pass = 0; pass < 3; ++pass) {
                const uint32_t(*pa)[4] = (pass == 2) ? ql : qh;
                const uint32_t bbase = base + ((pass == 1) ? OFF_KLO : OFF_KHI)
                                     + (uint32_t)(h * 9216) + kofsK;
                #pragma unroll
                for (int kc = 0; kc < 4; ++kc) {
                    #pragma unroll
                    for (int ntp = 0; ntp < 4; ++ntp) {
                        uint32_t bfr[4];
                        ldsm4(bfr, bbase + (uint32_t)(ntp * 16 * 144 + kc * 32));
                        mma_bf16(sc[2 * ntp],     pa[kc], bfr[0], bfr[1]);
                        mma_bf16(sc[2 * ntp + 1], pa[kc], bfr[2], bfr[3]);
                    }
                }
            }

            // ---- mask + exp + direct attn write ----
            #pragma unroll
            for (int nt = 0; nt < 8; ++nt) {
                const size_t cg = (size_t)(k0 + h * 64 + nt * 8 + colL);
                const int2 m0 = *reinterpret_cast<const int2*>(mask + rowA * S_ + cg);
                const int2 m1 = *reinterpret_cast<const int2*>(mask + (rowA + 8) * S_ + cg);
                float e0 = m0.x ? 0.0f : __expf(sc[nt][0]);
                float e1 = m0.y ? 0.0f : __expf(sc[nt][1]);
                float e2 = m1.x ? 0.0f : __expf(sc[nt][2]);
                float e3 = m1.y ? 0.0f : __expf(sc[nt][3]);
                rs0 += e0 + e1; rs1 += e2 + e3;
                *reinterpret_cast<float2*>(attn_out + rowA * S_ + cg)       = make_float2(e0, e1);
                *reinterpret_cast<float2*>(attn_out + (rowA + 8) * S_ + cg) = make_float2(e2, e3);
                sc[nt][0] = e0; sc[nt][1] = e1; sc[nt][2] = e2; sc[nt][3] = e3;
            }

            // ---- repack P into bf16 hi/lo A fragments (C-layout == A-layout) ----
            uint32_t ph[4][4], pl[4][4];
            #pragma unroll
            for (int kcp = 0; kcp < 4; ++kcp) {
                #pragma unroll
                for (int f = 0; f < 4; ++f) {
                    const float* s = sc[2 * kcp + ((f & 2) ? 1 : 0)];
                    float x = s[(f & 1) ? 2 : 0], y = s[(f & 1) ? 3 : 1];
                    float hx = bfhi(x), hy = bfhi(y);
                    ph[kcp][f] = packbf(hx, hy);
                    pl[kcp][f] = packbf(x - hx, y - hy);
                }
            }

            // ---- P·V half: ctx += PhVh + PlVh + PhVl ----
            const uint32_t vhb = base + OFF_VHI + (uint32_t)(h * 9216) + kofsV;
            const uint32_t vlb = base + OFF_VLO + (uint32_t)(h * 9216) + kofsV;
            #pragma unroll
            for (int kcp = 0; kcp < 4; ++kcp) {
                uint32_t vf[4];
                #pragma unroll
                for (int ntp = 0; ntp < 4; ++ntp) {
                    ldsm4t(vf, vhb + (uint32_t)(kcp * 16 * 144 + ntp * 32));
                    mma_bf16(ctx[2 * ntp],     ph[kcp], vf[0], vf[1]);
                    mma_bf16(ctx[2 * ntp + 1], ph[kcp], vf[2], vf[3]);
                    mma_bf16(ctx[2 * ntp],     pl[kcp], vf[0], vf[1]);
                    mma_bf16(ctx[2 * ntp + 1], pl[kcp], vf[2], vf[3]);
                }
                #pragma unroll
                for (int ntp = 0; ntp < 4; ++ntp) {
                    ldsm4t(vf, vlb + (uint32_t)(kcp * 16 * 144 + ntp * 32));
                    mma_bf16(ctx[2 * ntp],     ph[kcp], vf[0], vf[1]);
                    mma_bf16(ctx[2 * ntp + 1], ph[kcp], vf[2], vf[3]);
                }
            }
        }
    }

    // ---- rowsums + normalized ctx ----
    rs0 += __shfl_xor_sync(0xffffffffu, rs0, 1);
    rs0 += __shfl_xor_sync(0xffffffffu, rs0, 2);
    rs1 += __shfl_xor_sync(0xffffffffu, rs1, 1);
    rs1 += __shfl_xor_sync(0xffffffffu, rs1, 2);
    __syncthreads();
    float* rsum = reinterpret_cast<float*>(smc + SM_RS);
    if ((lane & 3) == 0) {
        rsum[16 * w + (lane >> 2)]     = rs0;
        rsum[16 * w + (lane >> 2) + 8] = rs1;
    }
    __syncthreads();
    if (tid < BQ) g_rowsum[(size_t)b * S_ + q0 + tid] = rsum[tid];

    const float inv0 = 1.0f / rsum[16 * w + (lane >> 2)];
    const float inv1 = 1.0f / rsum[16 * w + (lane >> 2) + 8];
    #pragma unroll
    for (int nt = 0; nt < 8; ++nt) {
        int d = nt * 8 + colL;
        *reinterpret_cast<float2*>(ctx_out + rowA * D_HD + d) =
            make_float2(ctx[nt][0] * inv0, ctx[nt][1] * inv0);
        *reinterpret_cast<float2*>(ctx_out + (rowA + 8) * D_HD + d) =
            make_float2(ctx[nt][2] * inv1, ctx[nt][3] * inv1);
    }
}

__global__ void attn_norm_kernel(float* __restrict__ attn)
{
    const size_t n4 = (size_t)B_ * S_ * S_ / 4;
    for (size_t i = (size_t)blockIdx.x * blockDim.x + threadIdx.x;
         i < n4; i += (size_t)gridDim.x * blockDim.x) {
        float4 v = reinterpret_cast<const float4*>(attn)[i];
        size_t row = i >> 10;
        float s = __fdividef(1.0f, g_rowsum[row]);
        v.x *= s; v.y *= s; v.z *= s; v.w *= s;
        reinterpret_cast<float4*>(attn)[i] = v;
    }
}

extern "C" void kernel_launch(void* const* d_in, const int* in_sizes, int n_in,
                              void* d_out, int out_size)
{
    const float* Q = (const float*)d_in[0];
    const float* K = (const float*)d_in[1];
    const float* V = (const float*)d_in[2];
    const int* mask = (const int*)d_in[3];

    float* ctx_out  = (float*)d_out;
    float* attn_out = ctx_out + (size_t)B_ * S_ * D_HD;

    static bool attr_set = false;
    if (!attr_set) {
        cudaFuncSetAttribute(attn_hmma_kernel,
                             cudaFuncAttributeMaxDynamicSharedMemorySize, SM_TOT);
        attr_set = true;
    }

    prep_split_kernel<<<(B_ * S_ * D_HD / 4) / NTH, NTH>>>(K, V);
    dim3 grid(S_ / BQ, B_);
    attn_hmma_kernel<<<grid, NTH, SM_TOT>>>(Q, mask, ctx_out, attn_out);
    attn_norm_kernel<<<8192, 256>>>(attn_out);
}